// round 9
// baseline (speedup 1.0000x reference)
#include <cuda_runtime.h>

// Problem constants (fixed instance: B=2048, T=2048, H=51)
#define H_  51
#define HP  52          // padded hidden
#define JP  208         // 4*HP gate count
#define RR  16          // batch rows per CTA
#define NT  832         // threads per CTA (26 warps)
#define TT  2048
#define BB  2048
#define PS  20          // smem partial stride (conflict-free for 128-bit ops)

// Repacked weights (device globals; prep kernel fills them each launch)
__device__ float g_W1p[HP*JP];   // [k][j] layer-1 W_hh
__device__ float g_W2a[HP*JP];   // [k][j] layer-2 W_ih
__device__ float g_W2b[HP*JP];   // [k][j] layer-2 W_hh
__device__ float g_b1[JP];
__device__ float g_wx[JP];
__device__ float g_b2[JP];
__device__ float g_wlin[HP];
__device__ float g_blin[1];

__global__ void prep_kernel(const float* __restrict__ W_ih1, const float* __restrict__ W_hh1,
                            const float* __restrict__ b_ih1, const float* __restrict__ b_hh1,
                            const float* __restrict__ W_ih2, const float* __restrict__ W_hh2,
                            const float* __restrict__ b_ih2, const float* __restrict__ b_hh2,
                            const float* __restrict__ W_lin, const float* __restrict__ b_lin)
{
    int stride = gridDim.x * blockDim.x;
    int i0 = blockIdx.x * blockDim.x + threadIdx.x;
    for (int idx = i0; idx < HP*JP; idx += stride) {
        int k = idx / JP, j = idx % JP;
        int g = j / HP, n = j % HP;
        bool v = (n < H_) && (k < H_);
        int ro = g*H_ + n;
        g_W1p[idx] = v ? W_hh1[ro*H_ + k] : 0.f;
        g_W2a[idx] = v ? W_ih2[ro*H_ + k] : 0.f;
        g_W2b[idx] = v ? W_hh2[ro*H_ + k] : 0.f;
    }
    for (int j = i0; j < JP; j += stride) {
        int g = j / HP, n = j % HP;
        bool v = (n < H_);
        int ro = g*H_ + n;
        g_b1[j] = v ? (b_ih1[ro] + b_hh1[ro]) : 0.f;
        g_wx[j] = v ? W_ih1[ro] : 0.f;
        g_b2[j] = v ? (b_ih2[ro] + b_hh2[ro]) : 0.f;
    }
    for (int n = i0; n < HP; n += stride) g_wlin[n] = (n < H_) ? W_lin[n] : 0.f;
    if (i0 == 0) g_blin[0] = b_lin[0];
}

// HW tanh (single MUFU op)
__device__ __forceinline__ float tanha(float x) {
    float r; asm("tanh.approx.f32 %0, %1;" : "=f"(r) : "f"(x)); return r;
}
__device__ __forceinline__ float siga(float x) {
    return fmaf(0.5f, tanha(0.5f*x), 0.5f);
}

// ---- packed f32x2 helpers (PTX-only; ptxas won't auto-fuse) ----
__device__ __forceinline__ unsigned long long pk2(float w) {
    unsigned long long r;
    asm("mov.b64 %0, {%1, %1};" : "=l"(r) : "f"(w));
    return r;
}
__device__ __forceinline__ void fma2(unsigned long long& a, unsigned long long w, unsigned long long h) {
    asm("fma.rn.f32x2 %0, %1, %2, %3;" : "=l"(a) : "l"(w), "l"(h), "l"(a));
}

__global__ __launch_bounds__(NT, 1)
void lstm_kernel(const float* __restrict__ input, float* __restrict__ out)
{
    extern __shared__ float sm[];
    float* pp  = sm;                   // 1664*PS floats (shared by both phases)
    float* h1s = pp + 1664*PS;         // HP*RR  layout [k][r]
    float* h2s = h1s + HP*RR;
    float* xs  = h2s + HP*RR;          // RR
    float* wls = xs + RR;              // HP
    float* b2s = wls + HP;             // JP

    const int tid  = threadIdx.x;
    const int row0 = blockIdx.x * RR;

    // phase-1 task (all threads): k-13-chunk kq1 (warp-uniform), gate row j1
    const int kq1 = tid / JP;               // 0..3
    const int j1  = tid - kq1*JP;           // 0..207
    // phase-2 task (all threads): g8 = src*4+kq2 (warp-uniform), j-pair (jp, jp+104)
    const int g8  = tid / 104;              // 0..7
    const int jp  = tid - g8*104;           // 0..103
    const int src = g8 >> 2;                // 0 = W_ih2·h1, 1 = W_hh2·h2
    const int kq2 = g8 & 3;                 // 0..3
    // update task (1:1): cell un, row ur
    const int un  = tid >> 4, ur = tid & 15;

    // phase-2 weights in registers (26); phase-1 weights streamed from L1
    float w2[26];
    {
        const float* Ws = src ? g_W2b : g_W2a;
#pragma unroll
        for (int kk = 0; kk < 13; kk++) {
            w2[kk]      = Ws[(kq2*13 + kk)*JP + jp];
            w2[13 + kk] = Ws[(kq2*13 + kk)*JP + jp + 104];
        }
    }
    const float* w1p = g_W1p + kq1*13*JP + j1;   // stride JP per k
    const float blin = g_blin[0];

    float c1 = 0.f, c2 = 0.f;

    for (int i = tid; i < HP*RR; i += NT) { h1s[i] = 0.f; h2s[i] = 0.f; }
    for (int i = tid; i < HP; i += NT) wls[i] = g_wlin[i];
    for (int i = tid; i < JP; i += NT) b2s[i] = g_b2[i];
    if (tid >= RR && tid < 2*RR) xs[tid - RR] = input[(row0 + tid - RR)*TT + 0];
    __syncthreads();

    for (int t = 0; t < TT; t++) {
        // prefetch next x (threads 16..31), held across the step
        float xnext = 0.f;
        if (tid >= RR && tid < 2*RR && (t + 1) < TT)
            xnext = __ldg(&input[(row0 + tid - RR)*TT + t + 1]);

        // ---- slot A: out(t-1) on threads 0..15, then phase1(t) on ALL threads ----
        if (tid < RR && t > 0) {
            float s0 = 0.f, s1 = 0.f, s2 = 0.f, s3 = 0.f;
#pragma unroll
            for (int n = 0; n < HP; n += 4) {
                s0 = fmaf(wls[n+0], h2s[(n+0)*RR + tid], s0);
                s1 = fmaf(wls[n+1], h2s[(n+1)*RR + tid], s1);
                s2 = fmaf(wls[n+2], h2s[(n+2)*RR + tid], s2);
                s3 = fmaf(wls[n+3], h2s[(n+3)*RR + tid], s3);
            }
            out[(row0 + tid)*TT + (t - 1)] = (s0 + s1) + (s2 + s3) + blin;
        }
        // phase1: G=1, K=13, weights via L1-hot LDG
        {
            unsigned long long acc[8];
            if (kq1 == 0) {
                unsigned long long bp = pk2(__ldg(&g_b1[j1]));
                unsigned long long wp = pk2(__ldg(&g_wx[j1]));
                const ulonglong2* xv = reinterpret_cast<const ulonglong2*>(xs);
#pragma unroll
                for (int rv = 0; rv < 4; rv++) {
                    ulonglong2 x2 = xv[rv];
                    acc[2*rv+0] = bp; fma2(acc[2*rv+0], wp, x2.x);
                    acc[2*rv+1] = bp; fma2(acc[2*rv+1], wp, x2.y);
                }
            } else {
#pragma unroll
                for (int k = 0; k < 8; k++) acc[k] = 0ULL;
            }
            const ulonglong2* hb = reinterpret_cast<const ulonglong2*>(h1s + kq1*13*RR);
#pragma unroll
            for (int kk = 0; kk < 13; kk++) {
                unsigned long long w = pk2(__ldg(w1p + kk*JP));
#pragma unroll
                for (int rv = 0; rv < 4; rv++) {
                    ulonglong2 h = hb[kk*4 + rv];
                    fma2(acc[2*rv+0], w, h.x);
                    fma2(acc[2*rv+1], w, h.y);
                }
            }
            ulonglong2* pw = reinterpret_cast<ulonglong2*>(pp + (kq1*JP + j1)*PS);
#pragma unroll
            for (int rv = 0; rv < 4; rv++) {
                ulonglong2 v; v.x = acc[2*rv+0]; v.y = acc[2*rv+1];
                pw[rv] = v;
            }
        }
        __syncthreads();

        // ---- update1(t): gates1 from 4 kq partials ----
        {
            int n = un;
            float gi = (pp[(0*JP + 0*HP+n)*PS + ur] + pp[(1*JP + 0*HP+n)*PS + ur])
                     + (pp[(2*JP + 0*HP+n)*PS + ur] + pp[(3*JP + 0*HP+n)*PS + ur]);
            float gf = (pp[(0*JP + 1*HP+n)*PS + ur] + pp[(1*JP + 1*HP+n)*PS + ur])
                     + (pp[(2*JP + 1*HP+n)*PS + ur] + pp[(3*JP + 1*HP+n)*PS + ur]);
            float gg = (pp[(0*JP + 2*HP+n)*PS + ur] + pp[(1*JP + 2*HP+n)*PS + ur])
                     + (pp[(2*JP + 2*HP+n)*PS + ur] + pp[(3*JP + 2*HP+n)*PS + ur]);
            float go = (pp[(0*JP + 3*HP+n)*PS + ur] + pp[(1*JP + 3*HP+n)*PS + ur])
                     + (pp[(2*JP + 3*HP+n)*PS + ur] + pp[(3*JP + 3*HP+n)*PS + ur]);
            c1 = siga(gf)*c1 + siga(gi)*tanha(gg);
            h1s[n*RR + ur] = siga(go)*tanha(c1);
        }
        __syncthreads();

        // ---- phase2(t): G=2, K=13, all threads ----
        {
            unsigned long long acc[16];
#pragma unroll
            for (int k = 0; k < 16; k++) acc[k] = 0ULL;
            const ulonglong2* hb =
                reinterpret_cast<const ulonglong2*>((src ? h2s : h1s) + kq2*13*RR);
#pragma unroll
            for (int kk = 0; kk < 13; kk++) {
                unsigned long long wA = pk2(w2[kk]);
                unsigned long long wB = pk2(w2[13 + kk]);
#pragma unroll
                for (int rv = 0; rv < 4; rv++) {
                    ulonglong2 h = hb[kk*4 + rv];
                    fma2(acc[2*rv+0],   wA, h.x);
                    fma2(acc[2*rv+1],   wA, h.y);
                    fma2(acc[8+2*rv+0], wB, h.x);
                    fma2(acc[8+2*rv+1], wB, h.y);
                }
            }
            ulonglong2* pwA = reinterpret_cast<ulonglong2*>(pp + (g8*JP + jp)*PS);
            ulonglong2* pwB = reinterpret_cast<ulonglong2*>(pp + (g8*JP + jp + 104)*PS);
#pragma unroll
            for (int rv = 0; rv < 4; rv++) {
                ulonglong2 vA; vA.x = acc[2*rv+0];   vA.y = acc[2*rv+1];   pwA[rv] = vA;
                ulonglong2 vB; vB.x = acc[8+2*rv+0]; vB.y = acc[8+2*rv+1]; pwB[rv] = vB;
            }
        }
        __syncthreads();

        // ---- update2(t): gates2 from 8 (src,kq) partials + bias; xs roll ----
        {
            int n = un;
            float gi = ((pp[(0*JP + 0*HP+n)*PS + ur] + pp[(1*JP + 0*HP+n)*PS + ur])
                      + (pp[(2*JP + 0*HP+n)*PS + ur] + pp[(3*JP + 0*HP+n)*PS + ur]))
                     + ((pp[(4*JP + 0*HP+n)*PS + ur] + pp[(5*JP + 0*HP+n)*PS + ur])
                      + (pp[(6*JP + 0*HP+n)*PS + ur] + pp[(7*JP + 0*HP+n)*PS + ur])) + b2s[0*HP+n];
            float gf = ((pp[(0*JP + 1*HP+n)*PS + ur] + pp[(1*JP + 1*HP+n)*PS + ur])
                      + (pp[(2*JP + 1*HP+n)*PS + ur] + pp[(3*JP + 1*HP+n)*PS + ur]))
                     + ((pp[(4*JP + 1*HP+n)*PS + ur] + pp[(5*JP + 1*HP+n)*PS + ur])
                      + (pp[(6*JP + 1*HP+n)*PS + ur] + pp[(7*JP + 1*HP+n)*PS + ur])) + b2s[1*HP+n];
            float gg = ((pp[(0*JP + 2*HP+n)*PS + ur] + pp[(1*JP + 2*HP+n)*PS + ur])
                      + (pp[(2*JP + 2*HP+n)*PS + ur] + pp[(3*JP + 2*HP+n)*PS + ur]))
                     + ((pp[(4*JP + 2*HP+n)*PS + ur] + pp[(5*JP + 2*HP+n)*PS + ur])
                      + (pp[(6*JP + 2*HP+n)*PS + ur] + pp[(7*JP + 2*HP+n)*PS + ur])) + b2s[2*HP+n];
            float go = ((pp[(0*JP + 3*HP+n)*PS + ur] + pp[(1*JP + 3*HP+n)*PS + ur])
                      + (pp[(2*JP + 3*HP+n)*PS + ur] + pp[(3*JP + 3*HP+n)*PS + ur]))
                     + ((pp[(4*JP + 3*HP+n)*PS + ur] + pp[(5*JP + 3*HP+n)*PS + ur])
                      + (pp[(6*JP + 3*HP+n)*PS + ur] + pp[(7*JP + 3*HP+n)*PS + ur])) + b2s[3*HP+n];
            c2 = siga(gf)*c2 + siga(gi)*tanha(gg);
            h2s[n*RR + ur] = siga(go)*tanha(c2);
        }
        if (tid >= RR && tid < 2*RR && (t + 1) < TT) xs[tid - RR] = xnext;
        __syncthreads();
    }

    // epilogue: out(TT-1)
    if (tid < RR) {
        float s0 = 0.f, s1 = 0.f, s2 = 0.f, s3 = 0.f;
#pragma unroll
        for (int n = 0; n < HP; n += 4) {
            s0 = fmaf(wls[n+0], h2s[(n+0)*RR + tid], s0);
            s1 = fmaf(wls[n+1], h2s[(n+1)*RR + tid], s1);
            s2 = fmaf(wls[n+2], h2s[(n+2)*RR + tid], s2);
            s3 = fmaf(wls[n+3], h2s[(n+3)*RR + tid], s3);
        }
        out[(row0 + tid)*TT + (TT - 1)] = (s0 + s1) + (s2 + s3) + blin;
    }
}

extern "C" void kernel_launch(void* const* d_in, const int* in_sizes, int n_in,
                              void* d_out, int out_size)
{
    const float* input = (const float*)d_in[0];
    const float* W_ih1 = (const float*)d_in[1];
    const float* W_hh1 = (const float*)d_in[2];
    const float* b_ih1 = (const float*)d_in[3];
    const float* b_hh1 = (const float*)d_in[4];
    const float* W_ih2 = (const float*)d_in[5];
    const float* W_hh2 = (const float*)d_in[6];
    const float* b_ih2 = (const float*)d_in[7];
    const float* b_hh2 = (const float*)d_in[8];
    const float* W_lin = (const float*)d_in[9];
    const float* b_lin = (const float*)d_in[10];
    float* out = (float*)d_out;

    const int smem_bytes = (1664*PS + HP*RR*2 + RR + HP + JP) * (int)sizeof(float);
    cudaFuncSetAttribute(lstm_kernel, cudaFuncAttributeMaxDynamicSharedMemorySize, smem_bytes);

    prep_kernel<<<64, 256>>>(W_ih1, W_hh1, b_ih1, b_hh1,
                             W_ih2, W_hh2, b_ih2, b_hh2, W_lin, b_lin);
    lstm_kernel<<<BB/RR, NT, smem_bytes>>>(input, out);
}

// round 12
// speedup vs baseline: 1.3794x; 1.3794x over previous
#include <cuda_runtime.h>

// Problem constants (fixed instance: B=2048, T=2048, H=51)
#define H_  51
#define HP  52          // padded hidden
#define JP  208         // 4*HP gate count
#define RR  16          // batch rows per CTA
#define NT  416         // threads per CTA (13 warps) -> 157 regs/thread budget
#define TT  2048
#define BB  2048
#define PS  20          // smem partial stride (conflict-free for 128-bit ops)

// Repacked weights (device globals; prep kernel fills them each launch)
__device__ float g_W1p[HP*JP];   // [k][j] layer-1 W_hh
__device__ float g_W2a[HP*JP];   // [k][j] layer-2 W_ih
__device__ float g_W2b[HP*JP];   // [k][j] layer-2 W_hh
__device__ float g_b1[JP];
__device__ float g_wx[JP];
__device__ float g_b2[JP];
__device__ float g_wlin[HP];
__device__ float g_blin[1];

__global__ void prep_kernel(const float* __restrict__ W_ih1, const float* __restrict__ W_hh1,
                            const float* __restrict__ b_ih1, const float* __restrict__ b_hh1,
                            const float* __restrict__ W_ih2, const float* __restrict__ W_hh2,
                            const float* __restrict__ b_ih2, const float* __restrict__ b_hh2,
                            const float* __restrict__ W_lin, const float* __restrict__ b_lin)
{
    int stride = gridDim.x * blockDim.x;
    int i0 = blockIdx.x * blockDim.x + threadIdx.x;
    for (int idx = i0; idx < HP*JP; idx += stride) {
        int k = idx / JP, j = idx % JP;
        int g = j / HP, n = j % HP;
        bool v = (n < H_) && (k < H_);
        int ro = g*H_ + n;
        g_W1p[idx] = v ? W_hh1[ro*H_ + k] : 0.f;
        g_W2a[idx] = v ? W_ih2[ro*H_ + k] : 0.f;
        g_W2b[idx] = v ? W_hh2[ro*H_ + k] : 0.f;
    }
    for (int j = i0; j < JP; j += stride) {
        int g = j / HP, n = j % HP;
        bool v = (n < H_);
        int ro = g*H_ + n;
        g_b1[j] = v ? (b_ih1[ro] + b_hh1[ro]) : 0.f;
        g_wx[j] = v ? W_ih1[ro] : 0.f;
        g_b2[j] = v ? (b_ih2[ro] + b_hh2[ro]) : 0.f;
    }
    for (int n = i0; n < HP; n += stride) g_wlin[n] = (n < H_) ? W_lin[n] : 0.f;
    if (i0 == 0) g_blin[0] = b_lin[0];
}

// HW tanh (single MUFU op)
__device__ __forceinline__ float tanha(float x) {
    float r; asm("tanh.approx.f32 %0, %1;" : "=f"(r) : "f"(x)); return r;
}
__device__ __forceinline__ float siga(float x) {
    return fmaf(0.5f, tanha(0.5f*x), 0.5f);
}

// ---- packed f32x2 helpers (PTX-only; ptxas won't auto-fuse) ----
__device__ __forceinline__ unsigned long long pk2(float w) {
    unsigned long long r;
    asm("mov.b64 %0, {%1, %1};" : "=l"(r) : "f"(w));
    return r;
}
__device__ __forceinline__ void fma2(unsigned long long& a, unsigned long long w, unsigned long long h) {
    asm("fma.rn.f32x2 %0, %1, %2, %3;" : "=l"(a) : "l"(w), "l"(h), "l"(a));
}

__global__ __launch_bounds__(NT, 1)
void lstm_kernel(const float* __restrict__ input, float* __restrict__ out)
{
    extern __shared__ float sm[];
    float* pp  = sm;                   // 832*PS floats (both phases alias it)
    float* h1s = pp + 832*PS;          // HP*RR  layout [k][r]
    float* h2s = h1s + HP*RR;
    float* xs  = h2s + HP*RR;          // RR
    float* wls = xs + RR;              // HP
    float* b2s = wls + HP;             // JP

    const int tid  = threadIdx.x;
    const int row0 = blockIdx.x * RR;

    // shared (q, jp) decomposition for BOTH phases; q in high bits (warp-uniform
    // except at 104-boundaries), j in low bits (broadcast-friendly)
    const int q   = tid / 104;              // 0..3
    const int jp  = tid - q*104;            // 0..103
    const int src = q >> 1;                 // phase2: 0 = W_ih2·h1, 1 = W_hh2·h2
    const int kh  = q & 1;                  // phase2 k-half
    // update tasks: cells (un, un+26), row ur — exactly 2 per thread, no guards
    const int un  = tid >> 4, ur = tid & 15;

    // register-resident weights for BOTH phases
    float w1[26];                           // phase1: G=2, K=13 (k-chunk q)
#pragma unroll
    for (int kk = 0; kk < 13; kk++) {
        w1[kk]      = g_W1p[(q*13 + kk)*JP + jp];
        w1[13 + kk] = g_W1p[(q*13 + kk)*JP + jp + 104];
    }
    float w2[52];                           // phase2: G=2, K=26 (src, kh)
    {
        const float* Ws = src ? g_W2b : g_W2a;
#pragma unroll
        for (int kk = 0; kk < 26; kk++) {
            w2[kk]      = Ws[(kh*26 + kk)*JP + jp];
            w2[26 + kk] = Ws[(kh*26 + kk)*JP + jp + 104];
        }
    }
    const float bias1a = g_b1[jp],  bias1b = g_b1[jp + 104];
    const float wxa    = g_wx[jp],  wxb    = g_wx[jp + 104];
    const float blin   = g_blin[0];

    // cell state: 2 cells per layer per thread
    float c1a = 0.f, c1b = 0.f, c2a = 0.f, c2b = 0.f;

    for (int i = tid; i < HP*RR; i += NT) { h1s[i] = 0.f; h2s[i] = 0.f; }
    for (int i = tid; i < HP; i += NT) wls[i] = g_wlin[i];
    for (int i = tid; i < JP; i += NT) b2s[i] = g_b2[i];
    if (tid >= RR && tid < 2*RR) xs[tid - RR] = input[(row0 + tid - RR)*TT + 0];
    __syncthreads();

    for (int t = 0; t < TT; t++) {
        // prefetch next x (threads 16..31), held across the step
        float xnext = 0.f;
        if (tid >= RR && tid < 2*RR && (t + 1) < TT)
            xnext = __ldg(&input[(row0 + tid - RR)*TT + t + 1]);

        // ---- slot 1: out(t-1) on warp 0 (split dot + shfl), phase1(t) on ALL ----
        if (tid < 32 && t > 0) {
            int r = tid & 15, hf = tid >> 4;   // hf: k-half of the output dot
            float s = 0.f;
            const float* wb = wls + hf*26;
            const float* hb = h2s + hf*26*RR;
#pragma unroll
            for (int n = 0; n < 26; n++) s = fmaf(wb[n], hb[n*RR + r], s);
            s += __shfl_xor_sync(0xffffffffu, s, 16);
            if (hf == 0) out[(row0 + r)*TT + (t - 1)] = s + blin;
        }
        // phase1(t): G=2, K=13, all 416 threads
        {
            unsigned long long acc[16];
            if (q == 0) {
                unsigned long long bpA = pk2(bias1a), wpA = pk2(wxa);
                unsigned long long bpB = pk2(bias1b), wpB = pk2(wxb);
                const ulonglong2* xv = reinterpret_cast<const ulonglong2*>(xs);
#pragma unroll
                for (int rv = 0; rv < 4; rv++) {
                    ulonglong2 x2 = xv[rv];
                    acc[2*rv+0] = bpA; fma2(acc[2*rv+0], wpA, x2.x);
                    acc[2*rv+1] = bpA; fma2(acc[2*rv+1], wpA, x2.y);
                    acc[8+2*rv+0] = bpB; fma2(acc[8+2*rv+0], wpB, x2.x);
                    acc[8+2*rv+1] = bpB; fma2(acc[8+2*rv+1], wpB, x2.y);
                }
            } else {
#pragma unroll
                for (int k = 0; k < 16; k++) acc[k] = 0ULL;
            }
            const ulonglong2* hb = reinterpret_cast<const ulonglong2*>(h1s + q*13*RR);
#pragma unroll
            for (int kk = 0; kk < 13; kk++) {
                unsigned long long wA = pk2(w1[kk]);
                unsigned long long wB = pk2(w1[13 + kk]);
#pragma unroll
                for (int rv = 0; rv < 4; rv++) {
                    ulonglong2 h = hb[kk*4 + rv];
                    fma2(acc[2*rv+0],   wA, h.x);
                    fma2(acc[2*rv+1],   wA, h.y);
                    fma2(acc[8+2*rv+0], wB, h.x);
                    fma2(acc[8+2*rv+1], wB, h.y);
                }
            }
            ulonglong2* pwA = reinterpret_cast<ulonglong2*>(pp + (q*JP + jp)*PS);
            ulonglong2* pwB = reinterpret_cast<ulonglong2*>(pp + (q*JP + jp + 104)*PS);
#pragma unroll
            for (int rv = 0; rv < 4; rv++) {
                ulonglong2 vA; vA.x = acc[2*rv+0];   vA.y = acc[2*rv+1];   pwA[rv] = vA;
                ulonglong2 vB; vB.x = acc[8+2*rv+0]; vB.y = acc[8+2*rv+1]; pwB[rv] = vB;
            }
        }
        __syncthreads();

        // ---- slot 2: update1(t), cells un and un+26, 4 kq partials per gate ----
        {
#pragma unroll
            for (int tsk = 0; tsk < 2; tsk++) {
                int n = un + tsk*26;
                float gi = (pp[(0*JP + 0*HP+n)*PS + ur] + pp[(1*JP + 0*HP+n)*PS + ur])
                         + (pp[(2*JP + 0*HP+n)*PS + ur] + pp[(3*JP + 0*HP+n)*PS + ur]);
                float gf = (pp[(0*JP + 1*HP+n)*PS + ur] + pp[(1*JP + 1*HP+n)*PS + ur])
                         + (pp[(2*JP + 1*HP+n)*PS + ur] + pp[(3*JP + 1*HP+n)*PS + ur]);
                float gg = (pp[(0*JP + 2*HP+n)*PS + ur] + pp[(1*JP + 2*HP+n)*PS + ur])
                         + (pp[(2*JP + 2*HP+n)*PS + ur] + pp[(3*JP + 2*HP+n)*PS + ur]);
                float go = (pp[(0*JP + 3*HP+n)*PS + ur] + pp[(1*JP + 3*HP+n)*PS + ur])
                         + (pp[(2*JP + 3*HP+n)*PS + ur] + pp[(3*JP + 3*HP+n)*PS + ur]);
                float c = tsk ? c1b : c1a;
                c = siga(gf)*c + siga(gi)*tanha(gg);
                if (tsk) c1b = c; else c1a = c;
                h1s[n*RR + ur] = siga(go)*tanha(c);
            }
        }
        __syncthreads();

        // ---- slot 3: phase2(t), G=2, K=26, all 416 threads ----
        {
            unsigned long long acc[16];
#pragma unroll
            for (int k = 0; k < 16; k++) acc[k] = 0ULL;
            const ulonglong2* hb =
                reinterpret_cast<const ulonglong2*>((src ? h2s : h1s) + kh*26*RR);
#pragma unroll
            for (int kk = 0; kk < 26; kk++) {
                unsigned long long wA = pk2(w2[kk]);
                unsigned long long wB = pk2(w2[26 + kk]);
#pragma unroll
                for (int rv = 0; rv < 4; rv++) {
                    ulonglong2 h = hb[kk*4 + rv];
                    fma2(acc[2*rv+0],   wA, h.x);
                    fma2(acc[2*rv+1],   wA, h.y);
                    fma2(acc[8+2*rv+0], wB, h.x);
                    fma2(acc[8+2*rv+1], wB, h.y);
                }
            }
            ulonglong2* pwA = reinterpret_cast<ulonglong2*>(pp + (q*JP + jp)*PS);
            ulonglong2* pwB = reinterpret_cast<ulonglong2*>(pp + (q*JP + jp + 104)*PS);
#pragma unroll
            for (int rv = 0; rv < 4; rv++) {
                ulonglong2 vA; vA.x = acc[2*rv+0];   vA.y = acc[2*rv+1];   pwA[rv] = vA;
                ulonglong2 vB; vB.x = acc[8+2*rv+0]; vB.y = acc[8+2*rv+1]; pwB[rv] = vB;
            }
        }
        __syncthreads();

        // ---- slot 4: update2(t), cells un and un+26, 4 q partials + bias ----
        {
#pragma unroll
            for (int tsk = 0; tsk < 2; tsk++) {
                int n = un + tsk*26;
                float gi = (pp[(0*JP + 0*HP+n)*PS + ur] + pp[(1*JP + 0*HP+n)*PS + ur])
                         + (pp[(2*JP + 0*HP+n)*PS + ur] + pp[(3*JP + 0*HP+n)*PS + ur]) + b2s[0*HP+n];
                float gf = (pp[(0*JP + 1*HP+n)*PS + ur] + pp[(1*JP + 1*HP+n)*PS + ur])
                         + (pp[(2*JP + 1*HP+n)*PS + ur] + pp[(3*JP + 1*HP+n)*PS + ur]) + b2s[1*HP+n];
                float gg = (pp[(0*JP + 2*HP+n)*PS + ur] + pp[(1*JP + 2*HP+n)*PS + ur])
                         + (pp[(2*JP + 2*HP+n)*PS + ur] + pp[(3*JP + 2*HP+n)*PS + ur]) + b2s[2*HP+n];
                float go = (pp[(0*JP + 3*HP+n)*PS + ur] + pp[(1*JP + 3*HP+n)*PS + ur])
                         + (pp[(2*JP + 3*HP+n)*PS + ur] + pp[(3*JP + 3*HP+n)*PS + ur]) + b2s[3*HP+n];
                float c = tsk ? c2b : c2a;
                c = siga(gf)*c + siga(gi)*tanha(gg);
                if (tsk) c2b = c; else c2a = c;
                h2s[n*RR + ur] = siga(go)*tanha(c);
            }
        }
        if (tid >= RR && tid < 2*RR && (t + 1) < TT) xs[tid - RR] = xnext;
        __syncthreads();
    }

    // epilogue: out(TT-1)
    if (tid < 32) {
        int r = tid & 15, hf = tid >> 4;
        float s = 0.f;
        const float* wb = wls + hf*26;
        const float* hb = h2s + hf*26*RR;
#pragma unroll
        for (int n = 0; n < 26; n++) s = fmaf(wb[n], hb[n*RR + r], s);
        s += __shfl_xor_sync(0xffffffffu, s, 16);
        if (hf == 0) out[(row0 + r)*TT + (TT - 1)] = s + blin;
    }
}

extern "C" void kernel_launch(void* const* d_in, const int* in_sizes, int n_in,
                              void* d_out, int out_size)
{
    const float* input = (const float*)d_in[0];
    const float* W_ih1 = (const float*)d_in[1];
    const float* W_hh1 = (const float*)d_in[2];
    const float* b_ih1 = (const float*)d_in[3];
    const float* b_hh1 = (const float*)d_in[4];
    const float* W_ih2 = (const float*)d_in[5];
    const float* W_hh2 = (const float*)d_in[6];
    const float* b_ih2 = (const float*)d_in[7];
    const float* b_hh2 = (const float*)d_in[8];
    const float* W_lin = (const float*)d_in[9];
    const float* b_lin = (const float*)d_in[10];
    float* out = (float*)d_out;

    const int smem_bytes = (832*PS + HP*RR*2 + RR + HP + JP) * (int)sizeof(float);
    cudaFuncSetAttribute(lstm_kernel, cudaFuncAttributeMaxDynamicSharedMemorySize, smem_bytes);

    prep_kernel<<<64, 256>>>(W_ih1, W_hh1, b_ih1, b_hh1,
                             W_ih2, W_hh2, b_ih2, b_hh2, W_lin, b_lin);
    lstm_kernel<<<BB/RR, NT, smem_bytes>>>(input, out);
}